// round 10
// baseline (speedup 1.0000x reference)
#include <cuda_runtime.h>
#include <math.h>

#define NPIX 4096   // H*W
#define NBH  4096   // B*HP

// Scratch (no allocation allowed -> __device__ globals)
__device__ float g_stats[NBH * 12];
__device__ float g_feat[NBH * 32];

__device__ __forceinline__ float wredsum(float v) {
#pragma unroll
    for (int o = 16; o; o >>= 1) v += __shfl_xor_sync(0xffffffffu, v, o);
    return v;
}

// FMA-only sigmoid: no MUFU. abs err < ~1e-6.
__device__ __forceinline__ float fsig(float x) {
    x = fmaxf(-18.f, fminf(18.f, x));
    float z = x * -1.4426950408889634f;
    float fz = z + 12582912.0f;
    int iz = __float_as_int(fz) - 0x4B400000;
    float zf = z - (float)iz;
    float p = 0.00133335581f;
    p = fmaf(p, zf, 0.00961812911f);
    p = fmaf(p, zf, 0.05550410866f);
    p = fmaf(p, zf, 0.24022650700f);
    p = fmaf(p, zf, 0.69314718056f);
    p = fmaf(p, zf, 1.0f);
    float scale = __int_as_float((iz + 127) << 23);
    float y = fmaf(p, scale, 1.0f);              // 1 + e^-x
    float r = __int_as_float(0x7EF311C3 - __float_as_int(y));
    r = r * (2.0f - y * r);
    r = r * (2.0f - y * r);
    r = r * (2.0f - y * r);
    return r;
}

// ============================================================================
// Kernel 1: stats, TWO slices per block (grid 2048). Slice-1 loads issued
// before slice-0's reduction tail so DRAM stays busy through the shuffles.
// ============================================================================
__global__ __launch_bounds__(256) void k_stats(const float* __restrict__ a,
                                               const float* __restrict__ b) {
    const int s0 = blockIdx.x * 2;
    const float4* a4 = (const float4*)a + s0 * 1024;
    const float4* b4 = (const float4*)b + s0 * 1024;
    const int t = threadIdx.x;
    const int wid = t >> 5, lane = t & 31;

    __shared__ float sh0[8][11];
    __shared__ float sh1[8][11];

    // issue ALL loads for both slices up front
    float4 va[4], vb[4], wa[4], wb[4];
#pragma unroll
    for (int k = 0; k < 4; k++) { va[k] = a4[t + k * 256]; vb[k] = b4[t + k * 256]; }
#pragma unroll
    for (int k = 0; k < 4; k++) { wa[k] = a4[1024 + t + k * 256]; wb[k] = b4[1024 + t + k * 256]; }

#define ACCUM(VA, VB)                                                     \
    {                                                                     \
        _Pragma("unroll")                                                 \
        for (int k = 0; k < 4; k++) {                                     \
            float xs[4] = {VA[k].x, VA[k].y, VA[k].z, VA[k].w};           \
            float ys[4] = {VB[k].x, VB[k].y, VB[k].z, VB[k].w};           \
            _Pragma("unroll")                                             \
            for (int e = 0; e < 4; e++) {                                 \
                float x = xs[e], y = ys[e];                               \
                sx += x; sxx += x * x; sy += y; syy += y * y; sxy += x * y; \
                float d = x - y; sd += d; sdd += d * d;                   \
                mnx = fminf(mnx, x); mxx = fmaxf(mxx, x);                 \
                mny = fminf(mny, y); mxy = fmaxf(mxy, y);                 \
            }                                                             \
        }                                                                 \
    }
#define WREDUCE_STORE(SH)                                                 \
    {                                                                     \
        _Pragma("unroll")                                                 \
        for (int o = 16; o; o >>= 1) {                                    \
            sx += __shfl_xor_sync(0xffffffffu, sx, o);                    \
            sxx += __shfl_xor_sync(0xffffffffu, sxx, o);                  \
            sy += __shfl_xor_sync(0xffffffffu, sy, o);                    \
            syy += __shfl_xor_sync(0xffffffffu, syy, o);                  \
            sxy += __shfl_xor_sync(0xffffffffu, sxy, o);                  \
            sd += __shfl_xor_sync(0xffffffffu, sd, o);                    \
            sdd += __shfl_xor_sync(0xffffffffu, sdd, o);                  \
            mnx = fminf(mnx, __shfl_xor_sync(0xffffffffu, mnx, o));       \
            mxx = fmaxf(mxx, __shfl_xor_sync(0xffffffffu, mxx, o));      \
            mny = fminf(mny, __shfl_xor_sync(0xffffffffu, mny, o));      \
            mxy = fmaxf(mxy, __shfl_xor_sync(0xffffffffu, mxy, o));      \
        }                                                                 \
        if (lane == 0) {                                                  \
            float* r = SH[wid];                                           \
            r[0] = sx; r[1] = sxx; r[2] = sy; r[3] = syy; r[4] = sxy;     \
            r[5] = sd; r[6] = sdd; r[7] = mnx; r[8] = mxx; r[9] = mny;    \
            r[10] = mxy;                                                  \
        }                                                                 \
    }

    {   // slice 0
        float sx = 0.f, sxx = 0.f, sy = 0.f, syy = 0.f, sxy = 0.f, sd = 0.f, sdd = 0.f;
        float mnx = INFINITY, mxx = -INFINITY, mny = INFINITY, mxy = -INFINITY;
        ACCUM(va, vb);
        WREDUCE_STORE(sh0);
    }
    {   // slice 1 (loads already in flight)
        float sx = 0.f, sxx = 0.f, sy = 0.f, syy = 0.f, sxy = 0.f, sd = 0.f, sdd = 0.f;
        float mnx = INFINITY, mxx = -INFINITY, mny = INFINITY, mxy = -INFINITY;
        ACCUM(wa, wb);
        WREDUCE_STORE(sh1);
    }
#undef ACCUM
#undef WREDUCE_STORE
    __syncthreads();

    // lanes 0..7 finalize slice0, lanes 8..15 finalize slice1
    if (t < 16) {
        const int sl = t >> 3, i = t & 7;
        const float (*sh)[11] = sl ? sh1 : sh0;
        float v0 = sh[i][0], v1 = sh[i][1], v2 = sh[i][2], v3 = sh[i][3], v4 = sh[i][4];
        float v5 = sh[i][5], v6 = sh[i][6];
        float m7 = sh[i][7], m8 = sh[i][8], m9 = sh[i][9], m10 = sh[i][10];
#pragma unroll
        for (int o = 4; o; o >>= 1) {   // xor stays within each 8-lane group
            v0 += __shfl_xor_sync(0xffffu, v0, o);
            v1 += __shfl_xor_sync(0xffffu, v1, o);
            v2 += __shfl_xor_sync(0xffffu, v2, o);
            v3 += __shfl_xor_sync(0xffffu, v3, o);
            v4 += __shfl_xor_sync(0xffffu, v4, o);
            v5 += __shfl_xor_sync(0xffffu, v5, o);
            v6 += __shfl_xor_sync(0xffffu, v6, o);
            m7 = fminf(m7, __shfl_xor_sync(0xffffu, m7, o));
            m8 = fmaxf(m8, __shfl_xor_sync(0xffffu, m8, o));
            m9 = fminf(m9, __shfl_xor_sync(0xffffu, m9, o));
            m10 = fmaxf(m10, __shfl_xor_sync(0xffffu, m10, o));
        }
        if (i == 0) {
            const float N = 4096.f, NM1 = 4095.f;
            float mean_a = v0 / N;
            float std_a = sqrtf(fmaxf(0.f, (v1 - v0 * v0 / N) / NM1));
            float mean_b = v2 / N;
            float std_b = sqrtf(fmaxf(0.f, (v3 - v2 * v2 / N) / NM1));
            float mean_d = v5 / N;
            float std_d = sqrtf(fmaxf(0.f, (v6 - v5 * v5 / N) / NM1));
            float norm_d = sqrtf(fmaxf(0.f, v6));
            float na = sqrtf(fmaxf(0.f, v1)), nb = sqrtf(fmaxf(0.f, v3));
            float cosv = v4 / (fmaxf(na, 1e-8f) * fmaxf(nb, 1e-8f));
            float* o = g_stats + (s0 + sl) * 12;
            o[0] = mean_a; o[1] = std_a; o[2] = m7; o[3] = m8;
            o[4] = mean_b; o[5] = std_b; o[6] = m9; o[7] = m10;
            o[8] = mean_d; o[9] = std_d; o[10] = norm_d; o[11] = cosv;
        }
    }
}

// ============================================================================
// Kernel 2: transformer core (unchanged from R9 — part of 81.9us baseline)
// ============================================================================
#define OFF_WINP  0
#define OFF_WQ    416
#define OFF_WKV   1568
#define OFF_WOUT  3872
#define OFF_WF1   5024
#define OFF_WF2   7328
#define OFF_STATS 9504
#define OFF_FEAT  10272
#define OFF_X     12320
#define OFF_KV    14624
#define OFF_PROBS 18976
#define SM_FLOATS 20000
#define XS 36

__global__ __launch_bounds__(512) void k_transformer(
    const float* __restrict__ layer_emb,
    const float* __restrict__ in_proj_w, const float* __restrict__ in_proj_b,
    const float* __restrict__ ln1_g, const float* __restrict__ ln1_b,
    const float* __restrict__ qkv_w, const float* __restrict__ qkv_b,
    const float* __restrict__ out_w, const float* __restrict__ out_b,
    const float* __restrict__ ln2_g, const float* __restrict__ ln2_b,
    const float* __restrict__ ffn_w1, const float* __restrict__ ffn_b1,
    const float* __restrict__ ffn_w2, const float* __restrict__ ffn_b2) {
    extern __shared__ float sm[];

    const int bidx = blockIdx.x >> 1;
    const int half = blockIdx.x & 1;
    const int t = threadIdx.x, lane = t & 31, wp = t >> 5;
    const int hp8 = t >> 3, jg = t & 7;
    const int lr = t >> 4, jgR = t & 15;
    const int rowR = half * 32 + lr;

    for (int o = t; o < 768; o += 512) sm[OFF_STATS + o] = g_stats[bidx * 768 + o];
    for (int o = t; o < 384; o += 512) sm[OFF_WINP + (o / 12) * 13 + (o % 12)] = in_proj_w[o];
    for (int o = t; o < 1024; o += 512) sm[OFF_WQ + (o >> 5) * 36 + (o & 31)] = qkv_w[o];
    for (int o = t; o < 2048; o += 512) sm[OFF_WKV + (o >> 5) * 36 + (o & 31)] = qkv_w[1024 + o];
    for (int o = t; o < 1024; o += 512) sm[OFF_WOUT + (o >> 5) * 36 + (o & 31)] = out_w[o];
    for (int o = t; o < 2048; o += 512) sm[OFF_WF1 + (o >> 5) * 36 + (o & 31)] = ffn_w1[o];
    for (int o = t; o < 2048; o += 512) sm[OFF_WF2 + (o >> 6) * 68 + (o & 63)] = ffn_w2[o];
    __syncthreads();

    for (int o = t; o < 2048; o += 512) {
        int hp = o >> 5, d = o & 31;
        float acc = in_proj_b[d] + layer_emb[d];
#pragma unroll
        for (int s = 0; s < 12; s++) acc += sm[OFF_STATS + hp * 12 + s] * sm[OFF_WINP + d * 13 + s];
        sm[OFF_FEAT + o] = acc;
    }
    __syncthreads();

#pragma unroll
    for (int rep = 0; rep < 4; rep++) {
        int hp = rep * 16 + wp;
        float v = sm[OFF_FEAT + hp * 32 + lane];
        float mu = wredsum(v) * (1.f / 32.f);
        float df = v - mu;
        float var = wredsum(df * df) * (1.f / 32.f);
        sm[OFF_X + hp * XS + lane] = df * rsqrtf(var + 1e-5f) * ln1_g[lane] + ln1_b[lane];
    }
    __syncthreads();

    float xr[32];
#define LOAD_XR(BASE)                                           \
    {                                                           \
        _Pragma("unroll")                                       \
        for (int k8 = 0; k8 < 8; k8++) {                        \
            float4 v = *(const float4*)&sm[(BASE) + k8 * 4];    \
            xr[k8 * 4 + 0] = v.x; xr[k8 * 4 + 1] = v.y;         \
            xr[k8 * 4 + 2] = v.z; xr[k8 * 4 + 3] = v.w;         \
        }                                                       \
    }
#define DOT32(ACC, WBASE)                                       \
    {                                                           \
        _Pragma("unroll")                                       \
        for (int k8 = 0; k8 < 8; k8++) {                        \
            float4 w4 = *(const float4*)&sm[(WBASE) + k8 * 4];  \
            ACC = fmaf(w4.x, xr[k8 * 4 + 0], ACC);              \
            ACC = fmaf(w4.y, xr[k8 * 4 + 1], ACC);              \
            ACC = fmaf(w4.z, xr[k8 * 4 + 2], ACC);              \
            ACC = fmaf(w4.w, xr[k8 * 4 + 3], ACC);              \
        }                                                       \
    }

    LOAD_XR(OFF_X + hp8 * XS);
#pragma unroll
    for (int jj = 0; jj < 8; jj++) {
        int j = jg + 8 * jj;
        float acc = qkv_b[32 + j];
        DOT32(acc, OFF_WKV + j * 36);
        sm[OFF_KV + hp8 * 65 + j] = acc;
    }
    const bool own = ((hp8 >> 5) == half);
    float qv[4];
    if (own) {
#pragma unroll
        for (int jj = 0; jj < 4; jj++) {
            int j = jg + 8 * jj;
            float acc = qkv_b[j];
            DOT32(acc, OFF_WQ + j * 36);
            qv[jj] = acc;
        }
    }
    __syncwarp();
    if (own) {
#pragma unroll
        for (int jj = 0; jj < 4; jj++) sm[OFF_X + hp8 * XS + jg + 8 * jj] = qv[jj];
    }
    __syncthreads();

    {
        const int dh = lane & 15, kvhalf = lane >> 4, hoff = kvhalf << 4;
        for (int c = 0; c < 4; c++) {
            int p = c * 16 + wp;
            int h = p >> 5, q = half * 32 + (p & 31);
            const float* qrow = &sm[OFF_X + q * XS + h * 16];
            float s0 = 0.f, s1 = 0.f;
#pragma unroll
            for (int d2 = 0; d2 < 16; d2++) {
                float qq = qrow[d2];
                s0 = fmaf(qq, sm[OFF_KV + lane * 65 + h * 16 + d2], s0);
                s1 = fmaf(qq, sm[OFF_KV + (lane + 32) * 65 + h * 16 + d2], s1);
            }
            float e0 = expf(s0 * 0.25f), e1 = expf(s1 * 0.25f);
            float inv = 1.f / wredsum(e0 + e1);
            sm[OFF_PROBS + wp * 64 + lane] = e0;
            sm[OFF_PROBS + wp * 64 + 32 + lane] = e1;
            __syncwarp();
            const float* pr = &sm[OFF_PROBS + wp * 64 + (kvhalf ? 32 : 0)];
            const float* vcol = &sm[OFF_KV + (kvhalf ? 32 * 65 : 0) + 32 + h * 16 + dh];
            float acc = 0.f;
#pragma unroll
            for (int k = 0; k < 32; k++) {
                int src = (k + hoff) & 31;
                acc = fmaf(pr[src], vcol[src * 65], acc);
            }
            acc += __shfl_xor_sync(0xffffffffu, acc, 16);
            if (lane < 16) sm[OFF_X + q * XS + h * 16 + lane] = acc * inv;
            __syncwarp();
        }
    }
    __syncthreads();

    LOAD_XR(OFF_X + rowR * XS);
#pragma unroll
    for (int jj = 0; jj < 2; jj++) {
        int j = jgR + 16 * jj;
        float acc = out_b[j];
        DOT32(acc, OFF_WOUT + j * 36);
        sm[OFF_FEAT + rowR * 32 + j] += acc;
    }
    __syncthreads();

#pragma unroll
    for (int rep = 0; rep < 2; rep++) {
        int hp = half * 32 + rep * 16 + wp;
        float v = sm[OFF_FEAT + hp * 32 + lane];
        float mu = wredsum(v) * (1.f / 32.f);
        float df = v - mu;
        float var = wredsum(df * df) * (1.f / 32.f);
        sm[OFF_X + hp * XS + lane] = df * rsqrtf(var + 1e-5f) * ln2_g[lane] + ln2_b[lane];
    }
    __syncthreads();

    LOAD_XR(OFF_X + rowR * XS);
#pragma unroll
    for (int jj = 0; jj < 4; jj++) {
        int f = jgR + 16 * jj;
        float acc = ffn_b1[f];
        DOT32(acc, OFF_WF1 + f * 36);
        sm[OFF_KV + lr * 68 + f] = 0.5f * acc * (1.f + erff(acc * 0.70710678118654752f));
    }
    __syncwarp();

#pragma unroll
    for (int jj = 0; jj < 2; jj++) {
        int d = jgR + 16 * jj;
        float acc = ffn_b2[d];
#pragma unroll
        for (int k8 = 0; k8 < 16; k8++) {
            float4 h4 = *(const float4*)&sm[OFF_KV + lr * 68 + k8 * 4];
            float4 w4 = *(const float4*)&sm[OFF_WF2 + d * 68 + k8 * 4];
            acc = fmaf(w4.x, h4.x, acc);
            acc = fmaf(w4.y, h4.y, acc);
            acc = fmaf(w4.z, h4.z, acc);
            acc = fmaf(w4.w, h4.w, acc);
        }
        g_feat[bidx * 2048 + rowR * 32 + d] = sm[OFF_FEAT + rowR * 32 + d] + acc;
    }
#undef LOAD_XR
#undef DOT32
}

// ============================================================================
// Kernel 3: heads + merge, TWO slices per block (grid 2048, reversed).
// 8 warps = 4 matrices x 2 slices in head phase; both slices' loads issued
// before the first slice's compute.
// ============================================================================
__global__ __launch_bounds__(256) void k_merge(
    const float* __restrict__ a, const float* __restrict__ b,
    float* __restrict__ out,
    const float* __restrict__ gate_w, const float* __restrict__ gate_b,
    const float* __restrict__ row_w, const float* __restrict__ row_b,
    const float* __restrict__ col_w, const float* __restrict__ col_b,
    const float* __restrict__ drow_w, const float* __restrict__ drow_b,
    const float* __restrict__ dcol_w, const float* __restrict__ dcol_b,
    const float* __restrict__ delta_scale) {
    const int pair = 2047 - blockIdx.x;     // reversed: reuse k1's L2 tail
    const int s0 = pair * 2;
    const int t = threadIdx.x, lane = t & 31, wp = t >> 5;

    __shared__ float s_feat[2][32];
    __shared__ float s_r[2][64], s_c[2][64], s_dr[2][64], s_dc[2][64];
    __shared__ float s_gate[2];

    if (t < 64) s_feat[t >> 5][t & 31] = g_feat[s0 * 32 + t];
    __syncthreads();

    // Heads: warp wp -> slice (wp&1), matrix (wp>>1); 64 outputs per warp.
    {
        const int sl = wp & 1, mat = wp >> 1;
        const float* w; const float* bb; float* dst;
        if (mat == 0)      { w = row_w;  bb = row_b;  dst = s_r[sl]; }
        else if (mat == 1) { w = col_w;  bb = col_b;  dst = s_c[sl]; }
        else if (mat == 2) { w = drow_w; bb = drow_b; dst = s_dr[sl]; }
        else               { w = dcol_w; bb = dcol_b; dst = s_dc[sl]; }
        const int g = lane >> 3;
        const int dsub = lane & 7;
        float4 f4 = ((const float4*)s_feat[sl])[dsub];
        const float dscale = (mat == 2) ? *delta_scale : 1.f;
#pragma unroll
        for (int ii = 0; ii < 16; ii++) {
            int i = ii * 4 + g;
            float4 w4 = ((const float4*)w)[i * 8 + dsub];
            float v = w4.x * f4.x + w4.y * f4.y + w4.z * f4.z + w4.w * f4.w;
            v += __shfl_xor_sync(0xffffffffu, v, 1);
            v += __shfl_xor_sync(0xffffffffu, v, 2);
            v += __shfl_xor_sync(0xffffffffu, v, 4);
            if (dsub == 0) dst[i] = (v + bb[i]) * dscale;
        }
        if (mat == 0) {
            float gv = s_feat[sl][lane] * gate_w[lane];
            gv = wredsum(gv);
            if (lane == 0) s_gate[sl] = gv + gate_b[0];
        }
    }
    __syncthreads();

    const float4* a4 = (const float4*)a + s0 * 1024;
    const float4* b4 = (const float4*)b + s0 * 1024;
    float4* o4 = (float4*)out + s0 * 1024;

    // issue ALL loads for both slices, then compute/store each
    float4 va[4], vb[4], wa[4], wb[4];
#pragma unroll
    for (int k = 0; k < 4; k++) { va[k] = a4[t + k * 256]; vb[k] = b4[t + k * 256]; }
#pragma unroll
    for (int k = 0; k < 4; k++) { wa[k] = a4[1024 + t + k * 256]; wb[k] = b4[1024 + t + k * 256]; }

#define MERGE_SLICE(SL, VA, VB, OBASE)                                        \
    {                                                                         \
        const float gate = s_gate[SL];                                        \
        _Pragma("unroll")                                                     \
        for (int k = 0; k < 4; k++) {                                         \
            int p = t + k * 256;                                              \
            int i = p >> 4;                                                   \
            float g = gate + s_r[SL][i];                                      \
            float dr = s_dr[SL][i];                                           \
            float4 c4 = ((const float4*)s_c[SL])[p & 15];                     \
            float4 dc4 = ((const float4*)s_dc[SL])[p & 15];                   \
            float4 r;                                                         \
            { float m = fsig(g + c4.x); r.x = VB[k].x + m * (VA[k].x - VB[k].x) + dr * dc4.x; } \
            { float m = fsig(g + c4.y); r.y = VB[k].y + m * (VA[k].y - VB[k].y) + dr * dc4.y; } \
            { float m = fsig(g + c4.z); r.z = VB[k].z + m * (VA[k].z - VB[k].z) + dr * dc4.z; } \
            { float m = fsig(g + c4.w); r.w = VB[k].w + m * (VA[k].w - VB[k].w) + dr * dc4.w; } \
            __stcs(&o4[(OBASE) + p], r);                                      \
        }                                                                     \
    }
    MERGE_SLICE(0, va, vb, 0);
    MERGE_SLICE(1, wa, wb, 1024);
#undef MERGE_SLICE
}

// ============================================================================
extern "C" void kernel_launch(void* const* d_in, const int* in_sizes, int n_in,
                              void* d_out, int out_size) {
    const float* a = (const float*)d_in[0];
    const float* b = (const float*)d_in[1];

    const int smem_bytes = SM_FLOATS * 4;
    cudaFuncSetAttribute(k_transformer, cudaFuncAttributeMaxDynamicSharedMemorySize,
                         smem_bytes);

    k_stats<<<NBH / 2, 256>>>(a, b);

    k_transformer<<<128, 512, smem_bytes>>>(
        (const float*)d_in[2],
        (const float*)d_in[3], (const float*)d_in[4],
        (const float*)d_in[5], (const float*)d_in[6],
        (const float*)d_in[7], (const float*)d_in[8],
        (const float*)d_in[9], (const float*)d_in[10],
        (const float*)d_in[11], (const float*)d_in[12],
        (const float*)d_in[13], (const float*)d_in[14],
        (const float*)d_in[15], (const float*)d_in[16]);

    k_merge<<<NBH / 2, 256>>>(
        a, b, (float*)d_out,
        (const float*)d_in[17], (const float*)d_in[18],
        (const float*)d_in[19], (const float*)d_in[20],
        (const float*)d_in[21], (const float*)d_in[22],
        (const float*)d_in[23], (const float*)d_in[24],
        (const float*)d_in[25], (const float*)d_in[26],
        (const float*)d_in[27]);
}